// round 5
// baseline (speedup 1.0000x reference)
#include <cuda_runtime.h>
#include <cstdint>

#define NEN   64368
#define NREL  12
#define DIM   128
#define NB    8
#define NITEM 6924
#define NE    1000000
#define BATCH 128
#define SEQL  32

#define ND4   (NEN * (DIM / 4))   // float4 elements per (basis-slice / w-slice)

// ---------------- scratch (no cudaMalloc allowed) ----------------
__device__ __align__(16) float g_w[(size_t)NREL * NEN * DIM];    // 395 MB
__device__ __align__(16) float g_nodes[(size_t)NEN * DIM];
__device__ __align__(16) float g_u[BATCH * DIM];
__device__ int g_cnt[NEN];        // per-dst degree histogram
__device__ int g_off[NEN + 1];    // CSR offsets
__device__ int g_cur[NEN];        // scatter cursors
__device__ int g_sorted[NE];      // packed row index: type*NEN + src, CSR order

// ---------------- sort phase A: zero histogram ----------------
__global__ void k_zcnt() {
    int i = blockIdx.x * blockDim.x + threadIdx.x;
    if (i < NEN) g_cnt[i] = 0;
}

// ---------------- sort phase B: histogram of dst ----------------
__global__ void k_hist(const int* __restrict__ ei) {
    int e = blockIdx.x * blockDim.x + threadIdx.x;
    if (e < NE) atomicAdd(&g_cnt[__ldg(ei + NE + e)], 1);
}

// ---------------- sort phase C: exclusive scan (single block) ----------------
#define SCAN_T 1024
#define SCAN_C 63   // 1024*63 = 64512 >= NEN
__global__ void k_scan() {
    __shared__ int s[SCAN_T];
    int t = threadIdx.x;
    int lo = t * SCAN_C, hi = min(lo + SCAN_C, NEN);
    int sum = 0;
    for (int i = lo; i < hi; i++) sum += g_cnt[i];
    s[t] = sum;
    __syncthreads();
    for (int o = 1; o < SCAN_T; o <<= 1) {
        int v = (t >= o) ? s[t - o] : 0;
        __syncthreads();
        s[t] += v;
        __syncthreads();
    }
    int run = (t > 0) ? s[t - 1] : 0;
    for (int i = lo; i < hi; i++) {
        int c = g_cnt[i];
        g_off[i] = run;
        g_cur[i] = run;
        run += c;
    }
    if (t == SCAN_T - 1) g_off[NEN] = run;
}

// ---------------- sort phase D: scatter packed row indices ----------------
__global__ void k_scatter(const int* __restrict__ ei, const int* __restrict__ et) {
    int e = blockIdx.x * blockDim.x + threadIdx.x;
    if (e >= NE) return;
    int src = __ldg(ei + e);
    int dst = __ldg(ei + NE + e);
    int t   = __ldg(et + e);
    int pos = atomicAdd(&g_cur[dst], 1);
    g_sorted[pos] = t * NEN + src;
}

// ---------------- phase 1: w[r,n,d] = sum_b att[r,b] * basis[b,n,d] ----------------
__global__ void k_w(const float* __restrict__ basis, const float* __restrict__ att) {
    __shared__ float s_att[NREL * NB];
    int tid = threadIdx.x;
    if (tid < NREL * NB) s_att[tid] = att[tid];
    __syncthreads();

    int idx = blockIdx.x * blockDim.x + tid;
    if (idx >= ND4) return;

    const float4* b4 = (const float4*)basis;
    float4 bb[NB];
#pragma unroll
    for (int b = 0; b < NB; b++) bb[b] = __ldg(b4 + (size_t)b * ND4 + idx);

    float4* w4 = (float4*)g_w;
#pragma unroll
    for (int r = 0; r < NREL; r++) {
        float4 o = make_float4(0.f, 0.f, 0.f, 0.f);
#pragma unroll
        for (int b = 0; b < NB; b++) {
            float a = s_att[r * NB + b];
            o.x += a * bb[b].x;
            o.y += a * bb[b].y;
            o.z += a * bb[b].z;
            o.w += a * bb[b].w;
        }
        w4[(size_t)r * ND4 + idx] = o;
    }
}

// ---------------- phase 2: fused gather+aggregate+finalize (1 warp per dst) ----------------
__global__ void k_aggr(const float* __restrict__ root, const float* __restrict__ bias) {
    int dst  = (blockIdx.x * blockDim.x + threadIdx.x) >> 5;
    int lane = threadIdx.x & 31;
    if (dst >= NEN) return;

    int beg = __ldg(g_off + dst);
    int end = __ldg(g_off + dst + 1);

    const float4* w4 = (const float4*)g_w;
    float4 a0 = make_float4(0.f, 0.f, 0.f, 0.f);
    float4 a1 = make_float4(0.f, 0.f, 0.f, 0.f);

    int k = beg;
    for (; k + 1 < end; k += 2) {
        int i0 = __ldg(g_sorted + k);
        int i1 = __ldg(g_sorted + k + 1);
        float4 v0 = __ldg(w4 + (size_t)i0 * (DIM / 4) + lane);
        float4 v1 = __ldg(w4 + (size_t)i1 * (DIM / 4) + lane);
        a0.x += v0.x; a0.y += v0.y; a0.z += v0.z; a0.w += v0.w;
        a1.x += v1.x; a1.y += v1.y; a1.z += v1.z; a1.w += v1.w;
    }
    if (k < end) {
        int i0 = __ldg(g_sorted + k);
        float4 v0 = __ldg(w4 + (size_t)i0 * (DIM / 4) + lane);
        a0.x += v0.x; a0.y += v0.y; a0.z += v0.z; a0.w += v0.w;
    }

    float inv = 1.f / fmaxf((float)(end - beg), 1.f);
    float4 r  = __ldg((const float4*)root + dst * (DIM / 4) + lane);
    float4 bs = __ldg((const float4*)bias + lane);
    float4 o;
    o.x = (a0.x + a1.x) * inv + r.x + bs.x;
    o.y = (a0.y + a1.y) * inv + r.y + bs.y;
    o.z = (a0.z + a1.z) * inv + r.z + bs.z;
    o.w = (a0.w + a1.w) * inv + r.w + bs.w;
    ((float4*)g_nodes)[dst * (DIM / 4) + lane] = o;
}

// ---------------- phase 4: attention pooling (1 block per batch row) ----------------
__global__ void k_pool(const int* __restrict__ seed_ids, const int* __restrict__ seed_len,
                       const float* __restrict__ A, const float* __restrict__ bvec) {
    __shared__ float sh_h[SEQL][DIM];
    __shared__ float sh_t[SEQL][DIM + 1];
    __shared__ float sh_e[SEQL];
    __shared__ float sh_attn[SEQL];
    __shared__ int   sid[SEQL];

    int b = blockIdx.x;
    int j = threadIdx.x;
    int len = __ldg(seed_len + b);

    if (j < SEQL) sid[j] = __ldg(seed_ids + b * SEQL + j);
    __syncthreads();

#pragma unroll
    for (int l = 0; l < SEQL; l++)
        sh_h[l][j] = g_nodes[(size_t)sid[l] * DIM + j];
    __syncthreads();

    float pe[SEQL];
#pragma unroll
    for (int l = 0; l < SEQL; l++) pe[l] = 0.f;
    for (int d = 0; d < DIM; d++) {
        float a = __ldg(A + d * DIM + j);
#pragma unroll
        for (int l = 0; l < SEQL; l++) pe[l] += sh_h[l][d] * a;
    }
    float bv = __ldg(bvec + j);
#pragma unroll
    for (int l = 0; l < SEQL; l++) sh_t[l][j] = tanhf(pe[l]) * bv;
    __syncthreads();

    if (j < SEQL) {
        float s = 0.f;
        for (int d = 0; d < DIM; d++) s += sh_t[j][d];
        sh_e[j] = s;
    }
    __syncthreads();

    if (j < 32) {
        float val = (j < len) ? sh_e[j] : -1e30f;
        float m = val;
#pragma unroll
        for (int o = 16; o; o >>= 1) m = fmaxf(m, __shfl_xor_sync(0xffffffffu, m, o));
        float ex = (j < len) ? expf(val - m) : 0.f;
        float s = ex;
#pragma unroll
        for (int o = 16; o; o >>= 1) s += __shfl_xor_sync(0xffffffffu, s, o);
        sh_attn[j] = (len > 0) ? ex / s : 0.f;
    }
    __syncthreads();

    float u = 0.f;
#pragma unroll
    for (int l = 0; l < SEQL; l++) u += sh_attn[l] * sh_h[l][j];
    g_u[b * DIM + j] = u;
}

// ---------------- phase 5: scores = u @ nodes[:NITEM].T + out_bias ----------------
#define ITEMS 32
__global__ void k_score(const float* __restrict__ out_bias, float* __restrict__ out) {
    __shared__ float shn[ITEMS * DIM];
    __shared__ float shout[ITEMS][BATCH + 1];

    int tid = threadIdx.x;
    int i0  = blockIdx.x * ITEMS;

    for (int idx = tid; idx < ITEMS * DIM; idx += BATCH) {
        int it = idx >> 7, d = idx & 127;
        int item = i0 + it;
        shn[idx] = (item < NITEM) ? g_nodes[(size_t)item * DIM + d] : 0.f;
    }
    __syncthreads();

    float acc[ITEMS];
#pragma unroll
    for (int it = 0; it < ITEMS; it++) acc[it] = 0.f;

    const float4* u4   = (const float4*)(g_u + tid * DIM);
    const float4* shn4 = (const float4*)shn;
#pragma unroll 4
    for (int d4 = 0; d4 < DIM / 4; d4++) {
        float4 uv = u4[d4];
#pragma unroll
        for (int it = 0; it < ITEMS; it++) {
            float4 nv = shn4[it * (DIM / 4) + d4];
            acc[it] += uv.x * nv.x + uv.y * nv.y + uv.z * nv.z + uv.w * nv.w;
        }
    }

#pragma unroll
    for (int it = 0; it < ITEMS; it++) shout[it][tid] = acc[it];
    __syncthreads();

    for (int idx = tid; idx < BATCH * ITEMS; idx += BATCH) {
        int bb = idx >> 5, it = idx & 31;
        int item = i0 + it;
        if (item < NITEM)
            out[(size_t)bb * NITEM + item] = shout[it][bb] + __ldg(out_bias + item);
    }
}

// ---------------- launch ----------------
extern "C" void kernel_launch(void* const* d_in, const int* in_sizes, int n_in,
                              void* d_out, int out_size) {
    const int*   edge_idx  = (const int*)d_in[0];
    const int*   edge_type = (const int*)d_in[1];
    const int*   seed_ids  = (const int*)d_in[2];
    const int*   seed_len  = (const int*)d_in[3];
    const float* basis     = (const float*)d_in[5];
    const float* att       = (const float*)d_in[6];
    const float* root      = (const float*)d_in[7];
    const float* rgcn_bias = (const float*)d_in[8];
    const float* attn_a    = (const float*)d_in[9];
    const float* attn_b    = (const float*)d_in[10];
    const float* out_bias  = (const float*)d_in[11];
    float* out = (float*)d_out;

    k_zcnt   <<<(NEN + 255) / 256, 256>>>();
    k_hist   <<<(NE + 255) / 256, 256>>>(edge_idx);
    k_scan   <<<1, SCAN_T>>>();
    k_scatter<<<(NE + 255) / 256, 256>>>(edge_idx, edge_type);
    k_w      <<<(ND4 + 255) / 256, 256>>>(basis, att);
    k_aggr   <<<(NEN * 32 + 255) / 256, 256>>>(root, rgcn_bias);
    k_pool   <<<BATCH, DIM>>>(seed_ids, seed_len, attn_a, attn_b);
    k_score  <<<(NITEM + ITEMS - 1) / ITEMS, BATCH>>>(out_bias, out);
}

// round 9
// speedup vs baseline: 1.1370x; 1.1370x over previous
#include <cuda_runtime.h>
#include <cuda_bf16.h>
#include <cstdint>

#define NEN   64368
#define NREL  12
#define DIM   128
#define NB    8
#define NITEM 6924
#define NE    1000000
#define BATCH 128
#define SEQL  32

#define ND4   (NEN * (DIM / 4))   // 4-element groups per (basis-slice / w-slice)

// ---------------- scratch (no cudaMalloc allowed) ----------------
__device__ __align__(16) __nv_bfloat16 g_w[(size_t)NREL * NEN * DIM];  // 198 MB
__device__ __align__(16) float g_nodes[(size_t)NEN * DIM];
__device__ __align__(16) float g_u[BATCH * DIM];
__device__ int g_cnt[NEN];        // per-dst degree histogram
__device__ int g_off[NEN + 1];    // CSR offsets
__device__ int g_cur[NEN];        // scatter cursors
__device__ int g_sorted[NE];      // packed row index: type*NEN + src, CSR order

// ---------------- sort phase A: zero histogram ----------------
__global__ void k_zcnt() {
    int i = blockIdx.x * blockDim.x + threadIdx.x;
    if (i < NEN) g_cnt[i] = 0;
}

// ---------------- sort phase B: histogram of dst ----------------
__global__ void k_hist(const int* __restrict__ ei) {
    int e = blockIdx.x * blockDim.x + threadIdx.x;
    if (e < NE) atomicAdd(&g_cnt[__ldg(ei + NE + e)], 1);
}

// ---------------- sort phase C: exclusive scan (single block) ----------------
#define SCAN_T 1024
#define SCAN_C 63   // 1024*63 = 64512 >= NEN
__global__ void k_scan() {
    __shared__ int s[SCAN_T];
    int t = threadIdx.x;
    int lo = t * SCAN_C, hi = min(lo + SCAN_C, NEN);
    int sum = 0;
    for (int i = lo; i < hi; i++) sum += g_cnt[i];
    s[t] = sum;
    __syncthreads();
    for (int o = 1; o < SCAN_T; o <<= 1) {
        int v = (t >= o) ? s[t - o] : 0;
        __syncthreads();
        s[t] += v;
        __syncthreads();
    }
    int run = (t > 0) ? s[t - 1] : 0;
    for (int i = lo; i < hi; i++) {
        int c = g_cnt[i];
        g_off[i] = run;
        g_cur[i] = run;
        run += c;
    }
    if (t == SCAN_T - 1) g_off[NEN] = run;
}

// ---------------- sort phase D: scatter packed row indices ----------------
__global__ void k_scatter(const int* __restrict__ ei, const int* __restrict__ et) {
    int e = blockIdx.x * blockDim.x + threadIdx.x;
    if (e >= NE) return;
    int src = __ldg(ei + e);
    int dst = __ldg(ei + NE + e);
    int t   = __ldg(et + e);
    int pos = atomicAdd(&g_cur[dst], 1);
    g_sorted[pos] = t * NEN + src;
}

// ---------------- phase 1: w[r,n,d] = sum_b att[r,b] * basis[b,n,d] (bf16 out) ---
__global__ void k_w(const float* __restrict__ basis, const float* __restrict__ att) {
    __shared__ float s_att[NREL * NB];
    int tid = threadIdx.x;
    if (tid < NREL * NB) s_att[tid] = att[tid];
    __syncthreads();

    int idx = blockIdx.x * blockDim.x + tid;
    if (idx >= ND4) return;

    const float4* b4 = (const float4*)basis;
    float4 bb[NB];
#pragma unroll
    for (int b = 0; b < NB; b++) bb[b] = __ldg(b4 + (size_t)b * ND4 + idx);

    uint2* w2 = (uint2*)g_w;   // 4 bf16 per uint2, ND4 uint2 per relation slice
#pragma unroll
    for (int r = 0; r < NREL; r++) {
        float4 o = make_float4(0.f, 0.f, 0.f, 0.f);
#pragma unroll
        for (int b = 0; b < NB; b++) {
            float a = s_att[r * NB + b];
            o.x += a * bb[b].x;
            o.y += a * bb[b].y;
            o.z += a * bb[b].z;
            o.w += a * bb[b].w;
        }
        __nv_bfloat162 lo = __floats2bfloat162_rn(o.x, o.y);
        __nv_bfloat162 hi = __floats2bfloat162_rn(o.z, o.w);
        uint2 st;
        st.x = *(unsigned int*)&lo;
        st.y = *(unsigned int*)&hi;
        w2[(size_t)r * ND4 + idx] = st;
    }
}

// ---------------- phase 2: fused gather+aggregate+finalize (1 warp per dst) ------
__global__ void k_aggr(const float* __restrict__ root, const float* __restrict__ bias) {
    int dst  = (blockIdx.x * blockDim.x + threadIdx.x) >> 5;
    int lane = threadIdx.x & 31;
    if (dst >= NEN) return;

    int beg = __ldg(g_off + dst);
    int end = __ldg(g_off + dst + 1);

    const uint2* w2 = (const uint2*)g_w;   // each row = 32 uint2, lane -> one uint2
    float4 a0 = make_float4(0.f, 0.f, 0.f, 0.f);
    float4 a1 = make_float4(0.f, 0.f, 0.f, 0.f);

    int k = beg;
    for (; k + 1 < end; k += 2) {
        int i0 = __ldg(g_sorted + k);
        int i1 = __ldg(g_sorted + k + 1);
        uint2 v0 = __ldg(w2 + (size_t)i0 * 32 + lane);
        uint2 v1 = __ldg(w2 + (size_t)i1 * 32 + lane);
        float2 f0 = __bfloat1622float2(*(__nv_bfloat162*)&v0.x);
        float2 f1 = __bfloat1622float2(*(__nv_bfloat162*)&v0.y);
        float2 f2 = __bfloat1622float2(*(__nv_bfloat162*)&v1.x);
        float2 f3 = __bfloat1622float2(*(__nv_bfloat162*)&v1.y);
        a0.x += f0.x; a0.y += f0.y; a0.z += f1.x; a0.w += f1.y;
        a1.x += f2.x; a1.y += f2.y; a1.z += f3.x; a1.w += f3.y;
    }
    if (k < end) {
        int i0 = __ldg(g_sorted + k);
        uint2 v0 = __ldg(w2 + (size_t)i0 * 32 + lane);
        float2 f0 = __bfloat1622float2(*(__nv_bfloat162*)&v0.x);
        float2 f1 = __bfloat1622float2(*(__nv_bfloat162*)&v0.y);
        a0.x += f0.x; a0.y += f0.y; a0.z += f1.x; a0.w += f1.y;
    }

    float inv = 1.f / fmaxf((float)(end - beg), 1.f);
    float4 r  = __ldg((const float4*)root + dst * (DIM / 4) + lane);
    float4 bs = __ldg((const float4*)bias + lane);
    float4 o;
    o.x = (a0.x + a1.x) * inv + r.x + bs.x;
    o.y = (a0.y + a1.y) * inv + r.y + bs.y;
    o.z = (a0.z + a1.z) * inv + r.z + bs.z;
    o.w = (a0.w + a1.w) * inv + r.w + bs.w;
    ((float4*)g_nodes)[dst * (DIM / 4) + lane] = o;
}

// ---------------- phase 4: attention pooling (1 block per batch row) -------------
__global__ void k_pool(const int* __restrict__ seed_ids, const int* __restrict__ seed_len,
                       const float* __restrict__ A, const float* __restrict__ bvec) {
    __shared__ float sh_h[SEQL][DIM];
    __shared__ float sh_t[SEQL][DIM + 1];
    __shared__ float sh_e[SEQL];
    __shared__ float sh_attn[SEQL];
    __shared__ int   sid[SEQL];

    int b = blockIdx.x;
    int j = threadIdx.x;
    int len = __ldg(seed_len + b);

    if (j < SEQL) sid[j] = __ldg(seed_ids + b * SEQL + j);
    __syncthreads();

#pragma unroll
    for (int l = 0; l < SEQL; l++)
        sh_h[l][j] = g_nodes[(size_t)sid[l] * DIM + j];
    __syncthreads();

    float pe[SEQL];
#pragma unroll
    for (int l = 0; l < SEQL; l++) pe[l] = 0.f;
    for (int d = 0; d < DIM; d++) {
        float a = __ldg(A + d * DIM + j);
#pragma unroll
        for (int l = 0; l < SEQL; l++) pe[l] += sh_h[l][d] * a;
    }
    float bv = __ldg(bvec + j);
#pragma unroll
    for (int l = 0; l < SEQL; l++) sh_t[l][j] = tanhf(pe[l]) * bv;
    __syncthreads();

    if (j < SEQL) {
        float s = 0.f;
        for (int d = 0; d < DIM; d++) s += sh_t[j][d];
        sh_e[j] = s;
    }
    __syncthreads();

    if (j < 32) {
        float val = (j < len) ? sh_e[j] : -1e30f;
        float m = val;
#pragma unroll
        for (int o = 16; o; o >>= 1) m = fmaxf(m, __shfl_xor_sync(0xffffffffu, m, o));
        float ex = (j < len) ? expf(val - m) : 0.f;
        float s = ex;
#pragma unroll
        for (int o = 16; o; o >>= 1) s += __shfl_xor_sync(0xffffffffu, s, o);
        sh_attn[j] = (len > 0) ? ex / s : 0.f;
    }
    __syncthreads();

    float u = 0.f;
#pragma unroll
    for (int l = 0; l < SEQL; l++) u += sh_attn[l] * sh_h[l][j];
    g_u[b * DIM + j] = u;
}

// ---------------- phase 5: scores = u @ nodes[:NITEM].T + out_bias ---------------
#define ITEMS 32
__global__ void k_score(const float* __restrict__ out_bias, float* __restrict__ out) {
    __shared__ float shn[ITEMS * DIM];
    __shared__ float shout[ITEMS][BATCH + 1];

    int tid = threadIdx.x;
    int i0  = blockIdx.x * ITEMS;

    for (int idx = tid; idx < ITEMS * DIM; idx += BATCH) {
        int it = idx >> 7, d = idx & 127;
        int item = i0 + it;
        shn[idx] = (item < NITEM) ? g_nodes[(size_t)item * DIM + d] : 0.f;
    }
    __syncthreads();

    float acc[ITEMS];
#pragma unroll
    for (int it = 0; it < ITEMS; it++) acc[it] = 0.f;

    const float4* u4   = (const float4*)(g_u + tid * DIM);
    const float4* shn4 = (const float4*)shn;
#pragma unroll 4
    for (int d4 = 0; d4 < DIM / 4; d4++) {
        float4 uv = u4[d4];
#pragma unroll
        for (int it = 0; it < ITEMS; it++) {
            float4 nv = shn4[it * (DIM / 4) + d4];
            acc[it] += uv.x * nv.x + uv.y * nv.y + uv.z * nv.z + uv.w * nv.w;
        }
    }

#pragma unroll
    for (int it = 0; it < ITEMS; it++) shout[it][tid] = acc[it];
    __syncthreads();

    for (int idx = tid; idx < BATCH * ITEMS; idx += BATCH) {
        int bb = idx >> 5, it = idx & 31;
        int item = i0 + it;
        if (item < NITEM)
            out[(size_t)bb * NITEM + item] = shout[it][bb] + __ldg(out_bias + item);
    }
}

// ---------------- launch (single stream — graph-capture safe) --------------------
extern "C" void kernel_launch(void* const* d_in, const int* in_sizes, int n_in,
                              void* d_out, int out_size) {
    const int*   edge_idx  = (const int*)d_in[0];
    const int*   edge_type = (const int*)d_in[1];
    const int*   seed_ids  = (const int*)d_in[2];
    const int*   seed_len  = (const int*)d_in[3];
    const float* basis     = (const float*)d_in[5];
    const float* att       = (const float*)d_in[6];
    const float* root      = (const float*)d_in[7];
    const float* rgcn_bias = (const float*)d_in[8];
    const float* attn_a    = (const float*)d_in[9];
    const float* attn_b    = (const float*)d_in[10];
    const float* out_bias  = (const float*)d_in[11];
    float* out = (float*)d_out;

    k_zcnt   <<<(NEN + 255) / 256, 256>>>();
    k_hist   <<<(NE + 255) / 256, 256>>>(edge_idx);
    k_scan   <<<1, SCAN_T>>>();
    k_scatter<<<(NE + 255) / 256, 256>>>(edge_idx, edge_type);
    k_w      <<<(ND4 + 255) / 256, 256>>>(basis, att);
    k_aggr   <<<(NEN * 32 + 255) / 256, 256>>>(root, rgcn_bias);
    k_pool   <<<BATCH, DIM>>>(seed_ids, seed_len, attn_a, attn_b);
    k_score  <<<(NITEM + ITEMS - 1) / ITEMS, BATCH>>>(out_bias, out);
}

// round 11
// speedup vs baseline: 1.1844x; 1.0416x over previous
#include <cuda_runtime.h>
#include <cstdint>

#define NEN   64368
#define NREL  12
#define DIM   128
#define NB    8
#define NITEM 6924
#define NE    1000000
#define BATCH 128
#define SEQL  32

#define ND4   (NEN * (DIM / 4))   // float4 count of a [NEN, DIM] array

// ---------------- scratch (no cudaMalloc allowed) ----------------
__device__ __align__(16) float g_aggr[(size_t)NEN * DIM];   // 33 MB (L2-resident)
__device__ __align__(16) float g_nodes[(size_t)NEN * DIM];
__device__ __align__(16) float g_u[BATCH * DIM];
__device__ int g_scnt[NEN];       // per-src out-degree histogram
__device__ int g_deg[NEN];        // per-dst in-degree (for mean)
__device__ int g_off[NEN + 1];    // CSR offsets by src
__device__ int g_cur[NEN];        // scatter cursors
__device__ int g_sorted[NE];      // packed (type<<16)|dst, grouped by src

// ---------------- phase 0: zero aggr + histograms ----------------
__global__ void k_zero() {
    int i = blockIdx.x * blockDim.x + threadIdx.x;
    if (i < ND4) ((float4*)g_aggr)[i] = make_float4(0.f, 0.f, 0.f, 0.f);
    if (i < NEN) { g_scnt[i] = 0; g_deg[i] = 0; }
}

// ---------------- phase A: histograms (4 edges/thread, int4 loads) ---------------
__global__ void k_hist(const int* __restrict__ ei) {
    int t = blockIdx.x * blockDim.x + threadIdx.x;
    if (t >= NE / 4) return;
    int4 s4 = __ldg((const int4*)ei + t);
    int4 d4 = __ldg((const int4*)(ei + NE) + t);
    atomicAdd(&g_scnt[s4.x], 1); atomicAdd(&g_scnt[s4.y], 1);
    atomicAdd(&g_scnt[s4.z], 1); atomicAdd(&g_scnt[s4.w], 1);
    atomicAdd(&g_deg[d4.x], 1);  atomicAdd(&g_deg[d4.y], 1);
    atomicAdd(&g_deg[d4.z], 1);  atomicAdd(&g_deg[d4.w], 1);
}

// ---------------- phase B: exclusive scan of src counts (single block) -----------
#define SCAN_T 1024
#define SCAN_C 63   // 1024*63 = 64512 >= NEN
__global__ void k_scan() {
    __shared__ int s[SCAN_T];
    int t = threadIdx.x;
    int lo = t * SCAN_C, hi = min(lo + SCAN_C, NEN);
    int sum = 0;
    for (int i = lo; i < hi; i++) sum += g_scnt[i];
    s[t] = sum;
    __syncthreads();
    for (int o = 1; o < SCAN_T; o <<= 1) {
        int v = (t >= o) ? s[t - o] : 0;
        __syncthreads();
        s[t] += v;
        __syncthreads();
    }
    int run = (t > 0) ? s[t - 1] : 0;
    for (int i = lo; i < hi; i++) {
        int c = g_scnt[i];
        g_off[i] = run;
        g_cur[i] = run;
        run += c;
    }
    if (t == SCAN_T - 1) g_off[NEN] = run;
}

// ---------------- phase C: scatter packed (type,dst), grouped by src -------------
__global__ void k_scatter(const int* __restrict__ ei, const int* __restrict__ et) {
    int t = blockIdx.x * blockDim.x + threadIdx.x;
    if (t >= NE / 4) return;
    int4 s4 = __ldg((const int4*)ei + t);
    int4 d4 = __ldg((const int4*)(ei + NE) + t);
    int4 t4 = __ldg((const int4*)et + t);
    int p;
    p = atomicAdd(&g_cur[s4.x], 1); g_sorted[p] = (t4.x << 16) | d4.x;
    p = atomicAdd(&g_cur[s4.y], 1); g_sorted[p] = (t4.y << 16) | d4.y;
    p = atomicAdd(&g_cur[s4.z], 1); g_sorted[p] = (t4.z << 16) | d4.z;
    p = atomicAdd(&g_cur[s4.w], 1); g_sorted[p] = (t4.w << 16) | d4.w;
}

// ---------------- phase D: fused msg-compute + scatter-add (1 warp per src) ------
__global__ void k_gather(const float* __restrict__ basis, const float* __restrict__ att) {
    __shared__ float s_att[NREL * NB];
    int tid = threadIdx.x;
    if (tid < NREL * NB) s_att[tid] = att[tid];
    __syncthreads();

    int src  = (blockIdx.x * blockDim.x + tid) >> 5;
    int lane = tid & 31;
    if (src >= NEN) return;

    int beg = __ldg(g_off + src);
    int end = __ldg(g_off + src + 1);
    if (beg == end) return;

    // load this src's 8 basis rows: basis[b, src, lane*4 .. lane*4+3]
    const float4* b4 = (const float4*)basis;
    float4 bb[NB];
#pragma unroll
    for (int b = 0; b < NB; b++)
        bb[b] = __ldg(b4 + ((size_t)b * NEN + src) * (DIM / 4) + lane);

    int k = beg;
    for (; k + 1 < end; k += 2) {
        int p0 = __ldg(g_sorted + k);
        int p1 = __ldg(g_sorted + k + 1);
        int t0 = p0 >> 16, d0 = p0 & 0xFFFF;
        int t1 = p1 >> 16, d1 = p1 & 0xFFFF;

        float4 m0 = make_float4(0.f, 0.f, 0.f, 0.f);
        float4 m1 = make_float4(0.f, 0.f, 0.f, 0.f);
#pragma unroll
        for (int b = 0; b < NB; b++) {
            float c0 = s_att[t0 * NB + b];
            float c1 = s_att[t1 * NB + b];
            m0.x += c0 * bb[b].x; m0.y += c0 * bb[b].y;
            m0.z += c0 * bb[b].z; m0.w += c0 * bb[b].w;
            m1.x += c1 * bb[b].x; m1.y += c1 * bb[b].y;
            m1.z += c1 * bb[b].z; m1.w += c1 * bb[b].w;
        }
        float* a0 = g_aggr + (size_t)d0 * DIM + lane * 4;
        float* a1 = g_aggr + (size_t)d1 * DIM + lane * 4;
        asm volatile("red.global.add.v4.f32 [%0], {%1,%2,%3,%4};"
                     :: "l"(a0), "f"(m0.x), "f"(m0.y), "f"(m0.z), "f"(m0.w) : "memory");
        asm volatile("red.global.add.v4.f32 [%0], {%1,%2,%3,%4};"
                     :: "l"(a1), "f"(m1.x), "f"(m1.y), "f"(m1.z), "f"(m1.w) : "memory");
    }
    if (k < end) {
        int p0 = __ldg(g_sorted + k);
        int t0 = p0 >> 16, d0 = p0 & 0xFFFF;
        float4 m0 = make_float4(0.f, 0.f, 0.f, 0.f);
#pragma unroll
        for (int b = 0; b < NB; b++) {
            float c0 = s_att[t0 * NB + b];
            m0.x += c0 * bb[b].x; m0.y += c0 * bb[b].y;
            m0.z += c0 * bb[b].z; m0.w += c0 * bb[b].w;
        }
        float* a0 = g_aggr + (size_t)d0 * DIM + lane * 4;
        asm volatile("red.global.add.v4.f32 [%0], {%1,%2,%3,%4};"
                     :: "l"(a0), "f"(m0.x), "f"(m0.y), "f"(m0.z), "f"(m0.w) : "memory");
    }
}

// ---------------- phase E: nodes = aggr/max(deg,1) + root + bias (float4) --------
__global__ void k_fin(const float* __restrict__ root, const float* __restrict__ bias) {
    int idx = blockIdx.x * blockDim.x + threadIdx.x;   // over ND4
    if (idx >= ND4) return;
    int node = idx >> 5;                                // 32 float4 per row
    float inv = 1.f / fmaxf((float)__ldg(g_deg + node), 1.f);
    float4 a  = ((const float4*)g_aggr)[idx];
    float4 r  = __ldg((const float4*)root + idx);
    float4 bs = __ldg((const float4*)bias + (idx & 31));
    float4 o;
    o.x = a.x * inv + r.x + bs.x;
    o.y = a.y * inv + r.y + bs.y;
    o.z = a.z * inv + r.z + bs.z;
    o.w = a.w * inv + r.w + bs.w;
    ((float4*)g_nodes)[idx] = o;
}

// ---------------- phase F: attention pooling (1 block per batch row) -------------
__global__ void k_pool(const int* __restrict__ seed_ids, const int* __restrict__ seed_len,
                       const float* __restrict__ A, const float* __restrict__ bvec) {
    __shared__ float sh_h[SEQL][DIM];
    __shared__ float sh_t[SEQL][DIM + 1];
    __shared__ float sh_e[SEQL];
    __shared__ float sh_attn[SEQL];
    __shared__ int   sid[SEQL];

    int b = blockIdx.x;
    int j = threadIdx.x;
    int len = __ldg(seed_len + b);

    if (j < SEQL) sid[j] = __ldg(seed_ids + b * SEQL + j);
    __syncthreads();

#pragma unroll
    for (int l = 0; l < SEQL; l++)
        sh_h[l][j] = g_nodes[(size_t)sid[l] * DIM + j];
    __syncthreads();

    float pe[SEQL];
#pragma unroll
    for (int l = 0; l < SEQL; l++) pe[l] = 0.f;
    for (int d = 0; d < DIM; d++) {
        float a = __ldg(A + d * DIM + j);
#pragma unroll
        for (int l = 0; l < SEQL; l++) pe[l] += sh_h[l][d] * a;
    }
    float bv = __ldg(bvec + j);
#pragma unroll
    for (int l = 0; l < SEQL; l++) sh_t[l][j] = tanhf(pe[l]) * bv;
    __syncthreads();

    if (j < SEQL) {
        float s = 0.f;
        for (int d = 0; d < DIM; d++) s += sh_t[j][d];
        sh_e[j] = s;
    }
    __syncthreads();

    if (j < 32) {
        float val = (j < len) ? sh_e[j] : -1e30f;
        float m = val;
#pragma unroll
        for (int o = 16; o; o >>= 1) m = fmaxf(m, __shfl_xor_sync(0xffffffffu, m, o));
        float ex = (j < len) ? expf(val - m) : 0.f;
        float s = ex;
#pragma unroll
        for (int o = 16; o; o >>= 1) s += __shfl_xor_sync(0xffffffffu, s, o);
        sh_attn[j] = (len > 0) ? ex / s : 0.f;
    }
    __syncthreads();

    float u = 0.f;
#pragma unroll
    for (int l = 0; l < SEQL; l++) u += sh_attn[l] * sh_h[l][j];
    g_u[b * DIM + j] = u;
}

// ---------------- phase G: scores = u @ nodes[:NITEM].T + out_bias ---------------
#define ITEMS 32
__global__ void k_score(const float* __restrict__ out_bias, float* __restrict__ out) {
    __shared__ float shn[ITEMS * DIM];
    __shared__ float shout[ITEMS][BATCH + 1];

    int tid = threadIdx.x;
    int i0  = blockIdx.x * ITEMS;

    for (int idx = tid; idx < ITEMS * DIM; idx += BATCH) {
        int it = idx >> 7, d = idx & 127;
        int item = i0 + it;
        shn[idx] = (item < NITEM) ? g_nodes[(size_t)item * DIM + d] : 0.f;
    }
    __syncthreads();

    float acc[ITEMS];
#pragma unroll
    for (int it = 0; it < ITEMS; it++) acc[it] = 0.f;

    const float4* u4   = (const float4*)(g_u + tid * DIM);
    const float4* shn4 = (const float4*)shn;
#pragma unroll 4
    for (int d4 = 0; d4 < DIM / 4; d4++) {
        float4 uv = u4[d4];
#pragma unroll
        for (int it = 0; it < ITEMS; it++) {
            float4 nv = shn4[it * (DIM / 4) + d4];
            acc[it] += uv.x * nv.x + uv.y * nv.y + uv.z * nv.z + uv.w * nv.w;
        }
    }

#pragma unroll
    for (int it = 0; it < ITEMS; it++) shout[it][tid] = acc[it];
    __syncthreads();

    for (int idx = tid; idx < BATCH * ITEMS; idx += BATCH) {
        int bb = idx >> 5, it = idx & 31;
        int item = i0 + it;
        if (item < NITEM)
            out[(size_t)bb * NITEM + item] = shout[it][bb] + __ldg(out_bias + item);
    }
}

// ---------------- launch (single stream — graph-capture safe) --------------------
extern "C" void kernel_launch(void* const* d_in, const int* in_sizes, int n_in,
                              void* d_out, int out_size) {
    const int*   edge_idx  = (const int*)d_in[0];
    const int*   edge_type = (const int*)d_in[1];
    const int*   seed_ids  = (const int*)d_in[2];
    const int*   seed_len  = (const int*)d_in[3];
    const float* basis     = (const float*)d_in[5];
    const float* att       = (const float*)d_in[6];
    const float* root      = (const float*)d_in[7];
    const float* rgcn_bias = (const float*)d_in[8];
    const float* attn_a    = (const float*)d_in[9];
    const float* attn_b    = (const float*)d_in[10];
    const float* out_bias  = (const float*)d_in[11];
    float* out = (float*)d_out;

    k_zero   <<<(ND4 + 255) / 256, 256>>>();
    k_hist   <<<(NE / 4 + 255) / 256, 256>>>(edge_idx);
    k_scan   <<<1, SCAN_T>>>();
    k_scatter<<<(NE / 4 + 255) / 256, 256>>>(edge_idx, edge_type);
    k_gather <<<(NEN * 32 + 255) / 256, 256>>>(basis, att);
    k_fin    <<<(ND4 + 255) / 256, 256>>>(root, rgcn_bias);
    k_pool   <<<BATCH, DIM>>>(seed_ids, seed_len, attn_a, attn_b);
    k_score  <<<(NITEM + ITEMS - 1) / ITEMS, BATCH>>>(out_bias, out);
}

// round 12
// speedup vs baseline: 1.5677x; 1.3236x over previous
#include <cuda_runtime.h>
#include <cstdint>

#define NEN   64368
#define NREL  12
#define DIM   128
#define NB    8
#define NITEM 6924
#define NE    1000000
#define BATCH 128
#define SEQL  32

// ---------------- scratch (no cudaMalloc allowed) ----------------
__device__ __align__(16) float g_aggr[(size_t)NEN * DIM];   // only needed rows touched
__device__ __align__(16) float g_nodes[(size_t)NEN * DIM];  // only needed rows written
__device__ __align__(16) float g_u[BATCH * DIM];
__device__ int g_need[NEN];       // 1 if node row is live (item or seed)
__device__ int g_scnt[NEN];       // per-src filtered out-degree
__device__ int g_deg[NEN];        // per-dst filtered in-degree (== full in-degree for live dst)
__device__ int g_off[NEN + 1];    // CSR offsets by src (filtered edges)
__device__ int g_cur[NEN];        // scatter cursors
__device__ int g_sorted[NE];      // packed (type<<16)|dst, grouped by src

// ---------------- phase 0: init masks/counters + zero live aggr rows -------------
// grid covers NITEM*32 (float4 zero of aggr rows < NITEM) and NEN (flags)
__global__ void k_prep() {
    int i = blockIdx.x * blockDim.x + threadIdx.x;
    if (i < NEN) {
        g_scnt[i] = 0;
        g_deg[i]  = 0;
        g_need[i] = (i < NITEM) ? 1 : 0;
    }
    if (i < NITEM * (DIM / 4))
        ((float4*)g_aggr)[i] = make_float4(0.f, 0.f, 0.f, 0.f);
}

// ---------------- phase 1: mark seed rows (handles seeds >= NITEM robustly) ------
__global__ void k_mark(const int* __restrict__ seed_ids) {
    int i = blockIdx.x * blockDim.x + threadIdx.x;
    if (i >= BATCH * SEQL) return;
    int id = __ldg(seed_ids + i);
    if (id >= NITEM && id < NEN) {
        if (atomicExch(&g_need[id], 1) == 0) {
            float4* row = (float4*)(g_aggr + (size_t)id * DIM);
            for (int j = 0; j < DIM / 4; j++) row[j] = make_float4(0.f, 0.f, 0.f, 0.f);
        }
    }
}

// ---------------- phase 2: filtered histograms (4 edges/thread) ------------------
__global__ void k_hist(const int* __restrict__ ei) {
    int t = blockIdx.x * blockDim.x + threadIdx.x;
    if (t >= NE / 4) return;
    int4 s4 = __ldg((const int4*)ei + t);
    int4 d4 = __ldg((const int4*)(ei + NE) + t);
    if (__ldg(g_need + d4.x)) { atomicAdd(&g_scnt[s4.x], 1); atomicAdd(&g_deg[d4.x], 1); }
    if (__ldg(g_need + d4.y)) { atomicAdd(&g_scnt[s4.y], 1); atomicAdd(&g_deg[d4.y], 1); }
    if (__ldg(g_need + d4.z)) { atomicAdd(&g_scnt[s4.z], 1); atomicAdd(&g_deg[d4.z], 1); }
    if (__ldg(g_need + d4.w)) { atomicAdd(&g_scnt[s4.w], 1); atomicAdd(&g_deg[d4.w], 1); }
}

// ---------------- phase 3: exclusive scan of src counts (single block) -----------
#define SCAN_T 1024
#define SCAN_C 63   // 1024*63 = 64512 >= NEN
__global__ void k_scan() {
    __shared__ int s[SCAN_T];
    int t = threadIdx.x;
    int lo = t * SCAN_C, hi = min(lo + SCAN_C, NEN);
    int sum = 0;
    for (int i = lo; i < hi; i++) sum += g_scnt[i];
    s[t] = sum;
    __syncthreads();
    for (int o = 1; o < SCAN_T; o <<= 1) {
        int v = (t >= o) ? s[t - o] : 0;
        __syncthreads();
        s[t] += v;
        __syncthreads();
    }
    int run = (t > 0) ? s[t - 1] : 0;
    for (int i = lo; i < hi; i++) {
        int c = g_scnt[i];
        g_off[i] = run;
        g_cur[i] = run;
        run += c;
    }
    if (t == SCAN_T - 1) g_off[NEN] = run;
}

// ---------------- phase 4: filtered scatter, grouped by src ----------------------
__global__ void k_scatter(const int* __restrict__ ei, const int* __restrict__ et) {
    int t = blockIdx.x * blockDim.x + threadIdx.x;
    if (t >= NE / 4) return;
    int4 s4 = __ldg((const int4*)ei + t);
    int4 d4 = __ldg((const int4*)(ei + NE) + t);
    int4 t4 = __ldg((const int4*)et + t);
    int p;
    if (__ldg(g_need + d4.x)) { p = atomicAdd(&g_cur[s4.x], 1); g_sorted[p] = (t4.x << 16) | d4.x; }
    if (__ldg(g_need + d4.y)) { p = atomicAdd(&g_cur[s4.y], 1); g_sorted[p] = (t4.y << 16) | d4.y; }
    if (__ldg(g_need + d4.z)) { p = atomicAdd(&g_cur[s4.z], 1); g_sorted[p] = (t4.z << 16) | d4.z; }
    if (__ldg(g_need + d4.w)) { p = atomicAdd(&g_cur[s4.w], 1); g_sorted[p] = (t4.w << 16) | d4.w; }
}

// ---------------- phase 5: fused msg-compute + scatter-add (1 warp per src) ------
__global__ void k_gather(const float* __restrict__ basis, const float* __restrict__ att) {
    __shared__ float s_att[NREL * NB];
    int tid = threadIdx.x;
    if (tid < NREL * NB) s_att[tid] = att[tid];
    __syncthreads();

    int src  = (blockIdx.x * blockDim.x + tid) >> 5;
    int lane = tid & 31;
    if (src >= NEN) return;

    int beg = __ldg(g_off + src);
    int end = __ldg(g_off + src + 1);
    if (beg == end) return;

    // load this src's 8 basis rows: basis[b, src, lane*4 .. lane*4+3]
    const float4* b4 = (const float4*)basis;
    float4 bb[NB];
#pragma unroll
    for (int b = 0; b < NB; b++)
        bb[b] = __ldg(b4 + ((size_t)b * NEN + src) * (DIM / 4) + lane);

    for (int k = beg; k < end; k++) {
        int p0 = __ldg(g_sorted + k);
        int t0 = p0 >> 16, d0 = p0 & 0xFFFF;
        float4 m0 = make_float4(0.f, 0.f, 0.f, 0.f);
#pragma unroll
        for (int b = 0; b < NB; b++) {
            float c0 = s_att[t0 * NB + b];
            m0.x += c0 * bb[b].x; m0.y += c0 * bb[b].y;
            m0.z += c0 * bb[b].z; m0.w += c0 * bb[b].w;
        }
        float* a0 = g_aggr + (size_t)d0 * DIM + lane * 4;
        asm volatile("red.global.add.v4.f32 [%0], {%1,%2,%3,%4};"
                     :: "l"(a0), "f"(m0.x), "f"(m0.y), "f"(m0.z), "f"(m0.w) : "memory");
    }
}

// ---------------- phase 6: nodes = aggr/max(deg,1) + root + bias (live rows) -----
__global__ void k_fin(const float* __restrict__ root, const float* __restrict__ bias) {
    int idx = blockIdx.x * blockDim.x + threadIdx.x;   // over NEN * 32 float4s
    if (idx >= NEN * (DIM / 4)) return;
    int node = idx >> 5;
    if (!__ldg(g_need + node)) return;
    float inv = 1.f / fmaxf((float)__ldg(g_deg + node), 1.f);
    float4 a  = ((const float4*)g_aggr)[idx];
    float4 r  = __ldg((const float4*)root + idx);
    float4 bs = __ldg((const float4*)bias + (idx & 31));
    float4 o;
    o.x = a.x * inv + r.x + bs.x;
    o.y = a.y * inv + r.y + bs.y;
    o.z = a.z * inv + r.z + bs.z;
    o.w = a.w * inv + r.w + bs.w;
    ((float4*)g_nodes)[idx] = o;
}

// ---------------- phase 7: attention pooling (1 block per batch row) -------------
__global__ void k_pool(const int* __restrict__ seed_ids, const int* __restrict__ seed_len,
                       const float* __restrict__ A, const float* __restrict__ bvec) {
    __shared__ float sh_h[SEQL][DIM];
    __shared__ float sh_t[SEQL][DIM + 1];
    __shared__ float sh_e[SEQL];
    __shared__ float sh_attn[SEQL];
    __shared__ int   sid[SEQL];

    int b = blockIdx.x;
    int j = threadIdx.x;
    int len = __ldg(seed_len + b);

    if (j < SEQL) sid[j] = __ldg(seed_ids + b * SEQL + j);
    __syncthreads();

#pragma unroll
    for (int l = 0; l < SEQL; l++)
        sh_h[l][j] = g_nodes[(size_t)sid[l] * DIM + j];
    __syncthreads();

    float pe[SEQL];
#pragma unroll
    for (int l = 0; l < SEQL; l++) pe[l] = 0.f;
    for (int d = 0; d < DIM; d++) {
        float a = __ldg(A + d * DIM + j);
#pragma unroll
        for (int l = 0; l < SEQL; l++) pe[l] += sh_h[l][d] * a;
    }
    float bv = __ldg(bvec + j);
#pragma unroll
    for (int l = 0; l < SEQL; l++) sh_t[l][j] = tanhf(pe[l]) * bv;
    __syncthreads();

    if (j < SEQL) {
        float s = 0.f;
        for (int d = 0; d < DIM; d++) s += sh_t[j][d];
        sh_e[j] = s;
    }
    __syncthreads();

    if (j < 32) {
        float val = (j < len) ? sh_e[j] : -1e30f;
        float m = val;
#pragma unroll
        for (int o = 16; o; o >>= 1) m = fmaxf(m, __shfl_xor_sync(0xffffffffu, m, o));
        float ex = (j < len) ? expf(val - m) : 0.f;
        float s = ex;
#pragma unroll
        for (int o = 16; o; o >>= 1) s += __shfl_xor_sync(0xffffffffu, s, o);
        sh_attn[j] = (len > 0) ? ex / s : 0.f;
    }
    __syncthreads();

    float u = 0.f;
#pragma unroll
    for (int l = 0; l < SEQL; l++) u += sh_attn[l] * sh_h[l][j];
    g_u[b * DIM + j] = u;
}

// ---------------- phase 8: scores = u @ nodes[:NITEM].T + out_bias ---------------
#define ITEMS 32
__global__ void k_score(const float* __restrict__ out_bias, float* __restrict__ out) {
    __shared__ float shn[ITEMS * DIM];
    __shared__ float shout[ITEMS][BATCH + 1];

    int tid = threadIdx.x;
    int i0  = blockIdx.x * ITEMS;

    for (int idx = tid; idx < ITEMS * DIM; idx += BATCH) {
        int it = idx >> 7, d = idx & 127;
        int item = i0 + it;
        shn[idx] = (item < NITEM) ? g_nodes[(size_t)item * DIM + d] : 0.f;
    }
    __syncthreads();

    float acc[ITEMS];
#pragma unroll
    for (int it = 0; it < ITEMS; it++) acc[it] = 0.f;

    const float4* u4   = (const float4*)(g_u + tid * DIM);
    const float4* shn4 = (const float4*)shn;
#pragma unroll 4
    for (int d4 = 0; d4 < DIM / 4; d4++) {
        float4 uv = u4[d4];
#pragma unroll
        for (int it = 0; it < ITEMS; it++) {
            float4 nv = shn4[it * (DIM / 4) + d4];
            acc[it] += uv.x * nv.x + uv.y * nv.y + uv.z * nv.z + uv.w * nv.w;
        }
    }

#pragma unroll
    for (int it = 0; it < ITEMS; it++) shout[it][tid] = acc[it];
    __syncthreads();

    for (int idx = tid; idx < BATCH * ITEMS; idx += BATCH) {
        int bb = idx >> 5, it = idx & 31;
        int item = i0 + it;
        if (item < NITEM)
            out[(size_t)bb * NITEM + item] = shout[it][bb] + __ldg(out_bias + item);
    }
}

// ---------------- launch (single stream — graph-capture safe) --------------------
extern "C" void kernel_launch(void* const* d_in, const int* in_sizes, int n_in,
                              void* d_out, int out_size) {
    const int*   edge_idx  = (const int*)d_in[0];
    const int*   edge_type = (const int*)d_in[1];
    const int*   seed_ids  = (const int*)d_in[2];
    const int*   seed_len  = (const int*)d_in[3];
    const float* basis     = (const float*)d_in[5];
    const float* att       = (const float*)d_in[6];
    const float* root      = (const float*)d_in[7];
    const float* rgcn_bias = (const float*)d_in[8];
    const float* attn_a    = (const float*)d_in[9];
    const float* attn_b    = (const float*)d_in[10];
    const float* out_bias  = (const float*)d_in[11];
    float* out = (float*)d_out;

    int prep_n = NITEM * (DIM / 4) > NEN ? NITEM * (DIM / 4) : NEN;
    k_prep   <<<(prep_n + 255) / 256, 256>>>();
    k_mark   <<<(BATCH * SEQL + 255) / 256, 256>>>(seed_ids);
    k_hist   <<<(NE / 4 + 255) / 256, 256>>>(edge_idx);
    k_scan   <<<1, SCAN_T>>>();
    k_scatter<<<(NE / 4 + 255) / 256, 256>>>(edge_idx, edge_type);
    k_gather <<<(NEN * 32 + 255) / 256, 256>>>(basis, att);
    k_fin    <<<(NEN * (DIM / 4) + 255) / 256, 256>>>(root, rgcn_bias);
    k_pool   <<<BATCH, DIM>>>(seed_ids, seed_len, attn_a, attn_b);
    k_score  <<<(NITEM + ITEMS - 1) / ITEMS, BATCH>>>(out_bias, out);
}

// round 13
// speedup vs baseline: 2.3464x; 1.4967x over previous
#include <cuda_runtime.h>
#include <cstdint>

#define NEN   64368
#define NREL  12
#define DIM   128
#define NB    8
#define NITEM 6924
#define NE    1000000
#define BATCH 128
#define SEQL  32

#define SB    1024                       // scan block size
#define NBLK  ((NEN + SB - 1) / SB)      // 63 scan blocks

// ---------------- scratch (no cudaMalloc allowed) ----------------
__device__ __align__(16) float g_aggr[(size_t)NEN * DIM];   // only needed rows touched
__device__ __align__(16) float g_nodes[(size_t)NEN * DIM];  // only needed rows written
__device__ __align__(16) float g_u[BATCH * DIM];
__device__ int g_need[NEN];       // 1 if node row is live (item or seed)
__device__ int g_scnt[NEN];       // per-src filtered out-degree
__device__ int g_deg[NEN];        // per-dst filtered in-degree
__device__ int g_off[NEN + 1];    // CSR offsets by src (filtered edges)
__device__ int g_cur[NEN];        // scatter cursors
__device__ int g_sorted[NE];      // packed (type<<16)|dst, grouped by src
__device__ int g_tmp[NEN];        // per-element exclusive prefix within scan block
__device__ int g_bsum[NBLK];      // per-block sums
__device__ int g_boff[NBLK];      // exclusive scan of block sums

// ---------------- phase 0: init masks/counters + zero live aggr rows -------------
__global__ void k_prep() {
    int i = blockIdx.x * blockDim.x + threadIdx.x;
    if (i < NEN) {
        g_scnt[i] = 0;
        g_deg[i]  = 0;
        g_need[i] = (i < NITEM) ? 1 : 0;
    }
    if (i < NITEM * (DIM / 4))
        ((float4*)g_aggr)[i] = make_float4(0.f, 0.f, 0.f, 0.f);
}

// ---------------- phase 1: mark seed rows (handles seeds >= NITEM robustly) ------
__global__ void k_mark(const int* __restrict__ seed_ids) {
    int i = blockIdx.x * blockDim.x + threadIdx.x;
    if (i >= BATCH * SEQL) return;
    int id = __ldg(seed_ids + i);
    if (id >= NITEM && id < NEN) {
        if (atomicExch(&g_need[id], 1) == 0) {
            float4* row = (float4*)(g_aggr + (size_t)id * DIM);
            for (int j = 0; j < DIM / 4; j++) row[j] = make_float4(0.f, 0.f, 0.f, 0.f);
        }
    }
}

// ---------------- phase 2: filtered histograms (4 edges/thread) ------------------
__global__ void k_hist(const int* __restrict__ ei) {
    int t = blockIdx.x * blockDim.x + threadIdx.x;
    if (t >= NE / 4) return;
    int4 s4 = __ldg((const int4*)ei + t);
    int4 d4 = __ldg((const int4*)(ei + NE) + t);
    if (__ldg(g_need + d4.x)) { atomicAdd(&g_scnt[s4.x], 1); atomicAdd(&g_deg[d4.x], 1); }
    if (__ldg(g_need + d4.y)) { atomicAdd(&g_scnt[s4.y], 1); atomicAdd(&g_deg[d4.y], 1); }
    if (__ldg(g_need + d4.z)) { atomicAdd(&g_scnt[s4.z], 1); atomicAdd(&g_deg[d4.z], 1); }
    if (__ldg(g_need + d4.w)) { atomicAdd(&g_scnt[s4.w], 1); atomicAdd(&g_deg[d4.w], 1); }
}

// ---------------- phase 3a: per-block scan (63 blocks x 1024) --------------------
__global__ void k_scan1() {
    __shared__ int s[SB];
    int t = threadIdx.x;
    int g = blockIdx.x * SB + t;
    int v = (g < NEN) ? g_scnt[g] : 0;
    s[t] = v;
    __syncthreads();
#pragma unroll
    for (int o = 1; o < SB; o <<= 1) {
        int x = (t >= o) ? s[t - o] : 0;
        __syncthreads();
        s[t] += x;
        __syncthreads();
    }
    if (g < NEN) g_tmp[g] = s[t] - v;            // exclusive within block
    if (t == SB - 1) g_bsum[blockIdx.x] = s[t];  // block total
}

// ---------------- phase 3b: scan the 63 block sums (1 tiny block) ----------------
__global__ void k_scan2() {
    __shared__ int s[64];
    int t = threadIdx.x;  // 64 threads
    int v = (t < NBLK) ? g_bsum[t] : 0;
    s[t] = v;
    __syncthreads();
#pragma unroll
    for (int o = 1; o < 64; o <<= 1) {
        int x = (t >= o) ? s[t - o] : 0;
        __syncthreads();
        s[t] += x;
        __syncthreads();
    }
    if (t < NBLK) g_boff[t] = s[t] - v;          // exclusive
    if (t == 63) g_off[NEN] = s[63];             // grand total
}

// ---------------- phase 3c: add block offsets, emit g_off / g_cur ----------------
__global__ void k_scan3() {
    int g = blockIdx.x * blockDim.x + threadIdx.x;
    if (g >= NEN) return;
    int off = g_tmp[g] + __ldg(g_boff + (g / SB));
    g_off[g] = off;
    g_cur[g] = off;
}

// ---------------- phase 4: filtered scatter, grouped by src ----------------------
__global__ void k_scatter(const int* __restrict__ ei, const int* __restrict__ et) {
    int t = blockIdx.x * blockDim.x + threadIdx.x;
    if (t >= NE / 4) return;
    int4 s4 = __ldg((const int4*)ei + t);
    int4 d4 = __ldg((const int4*)(ei + NE) + t);
    int4 t4 = __ldg((const int4*)et + t);
    int p;
    if (__ldg(g_need + d4.x)) { p = atomicAdd(&g_cur[s4.x], 1); g_sorted[p] = (t4.x << 16) | d4.x; }
    if (__ldg(g_need + d4.y)) { p = atomicAdd(&g_cur[s4.y], 1); g_sorted[p] = (t4.y << 16) | d4.y; }
    if (__ldg(g_need + d4.z)) { p = atomicAdd(&g_cur[s4.z], 1); g_sorted[p] = (t4.z << 16) | d4.z; }
    if (__ldg(g_need + d4.w)) { p = atomicAdd(&g_cur[s4.w], 1); g_sorted[p] = (t4.w << 16) | d4.w; }
}

// ---------------- phase 5: fused msg-compute + scatter-add (1 warp per src) ------
__global__ void k_gather(const float* __restrict__ basis, const float* __restrict__ att) {
    __shared__ float s_att[NREL * NB];
    int tid = threadIdx.x;
    if (tid < NREL * NB) s_att[tid] = att[tid];
    __syncthreads();

    int src  = (blockIdx.x * blockDim.x + tid) >> 5;
    int lane = tid & 31;
    if (src >= NEN) return;

    int beg = __ldg(g_off + src);
    int end = __ldg(g_off + src + 1);
    if (beg == end) return;

    const float4* b4 = (const float4*)basis;
    float4 bb[NB];
#pragma unroll
    for (int b = 0; b < NB; b++)
        bb[b] = __ldg(b4 + ((size_t)b * NEN + src) * (DIM / 4) + lane);

    for (int k = beg; k < end; k++) {
        int p0 = __ldg(g_sorted + k);
        int t0 = p0 >> 16, d0 = p0 & 0xFFFF;
        float4 m0 = make_float4(0.f, 0.f, 0.f, 0.f);
#pragma unroll
        for (int b = 0; b < NB; b++) {
            float c0 = s_att[t0 * NB + b];
            m0.x += c0 * bb[b].x; m0.y += c0 * bb[b].y;
            m0.z += c0 * bb[b].z; m0.w += c0 * bb[b].w;
        }
        float* a0 = g_aggr + (size_t)d0 * DIM + lane * 4;
        asm volatile("red.global.add.v4.f32 [%0], {%1,%2,%3,%4};"
                     :: "l"(a0), "f"(m0.x), "f"(m0.y), "f"(m0.z), "f"(m0.w) : "memory");
    }
}

// ---------------- phase 6: nodes = aggr/max(deg,1) + root + bias (live rows) -----
__global__ void k_fin(const float* __restrict__ root, const float* __restrict__ bias) {
    int idx = blockIdx.x * blockDim.x + threadIdx.x;
    if (idx >= NEN * (DIM / 4)) return;
    int node = idx >> 5;
    if (!__ldg(g_need + node)) return;
    float inv = 1.f / fmaxf((float)__ldg(g_deg + node), 1.f);
    float4 a  = ((const float4*)g_aggr)[idx];
    float4 r  = __ldg((const float4*)root + idx);
    float4 bs = __ldg((const float4*)bias + (idx & 31));
    float4 o;
    o.x = a.x * inv + r.x + bs.x;
    o.y = a.y * inv + r.y + bs.y;
    o.z = a.z * inv + r.z + bs.z;
    o.w = a.w * inv + r.w + bs.w;
    ((float4*)g_nodes)[idx] = o;
}

// ---------------- phase 7: attention pooling (1 block per batch row) -------------
__global__ void k_pool(const int* __restrict__ seed_ids, const int* __restrict__ seed_len,
                       const float* __restrict__ A, const float* __restrict__ bvec) {
    __shared__ float sh_h[SEQL][DIM];
    __shared__ float sh_t[SEQL][DIM + 1];
    __shared__ float sh_e[SEQL];
    __shared__ float sh_attn[SEQL];
    __shared__ int   sid[SEQL];

    int b = blockIdx.x;
    int j = threadIdx.x;
    int len = __ldg(seed_len + b);

    if (j < SEQL) sid[j] = __ldg(seed_ids + b * SEQL + j);
    __syncthreads();

#pragma unroll
    for (int l = 0; l < SEQL; l++)
        sh_h[l][j] = g_nodes[(size_t)sid[l] * DIM + j];
    __syncthreads();

    float pe[SEQL];
#pragma unroll
    for (int l = 0; l < SEQL; l++) pe[l] = 0.f;
    for (int d = 0; d < DIM; d++) {
        float a = __ldg(A + d * DIM + j);
#pragma unroll
        for (int l = 0; l < SEQL; l++) pe[l] += sh_h[l][d] * a;
    }
    float bv = __ldg(bvec + j);
#pragma unroll
    for (int l = 0; l < SEQL; l++) sh_t[l][j] = tanhf(pe[l]) * bv;
    __syncthreads();

    if (j < SEQL) {
        float s = 0.f;
        for (int d = 0; d < DIM; d++) s += sh_t[j][d];
        sh_e[j] = s;
    }
    __syncthreads();

    if (j < 32) {
        float val = (j < len) ? sh_e[j] : -1e30f;
        float m = val;
#pragma unroll
        for (int o = 16; o; o >>= 1) m = fmaxf(m, __shfl_xor_sync(0xffffffffu, m, o));
        float ex = (j < len) ? expf(val - m) : 0.f;
        float s = ex;
#pragma unroll
        for (int o = 16; o; o >>= 1) s += __shfl_xor_sync(0xffffffffu, s, o);
        sh_attn[j] = (len > 0) ? ex / s : 0.f;
    }
    __syncthreads();

    float u = 0.f;
#pragma unroll
    for (int l = 0; l < SEQL; l++) u += sh_attn[l] * sh_h[l][j];
    g_u[b * DIM + j] = u;
}

// ---------------- phase 8: scores = u @ nodes[:NITEM].T + out_bias ---------------
#define ITEMS 32
__global__ void k_score(const float* __restrict__ out_bias, float* __restrict__ out) {
    __shared__ float shn[ITEMS * DIM];
    __shared__ float shout[ITEMS][BATCH + 1];

    int tid = threadIdx.x;
    int i0  = blockIdx.x * ITEMS;

    for (int idx = tid; idx < ITEMS * DIM; idx += BATCH) {
        int it = idx >> 7, d = idx & 127;
        int item = i0 + it;
        shn[idx] = (item < NITEM) ? g_nodes[(size_t)item * DIM + d] : 0.f;
    }
    __syncthreads();

    float acc[ITEMS];
#pragma unroll
    for (int it = 0; it < ITEMS; it++) acc[it] = 0.f;

    const float4* u4   = (const float4*)(g_u + tid * DIM);
    const float4* shn4 = (const float4*)shn;
#pragma unroll 4
    for (int d4 = 0; d4 < DIM / 4; d4++) {
        float4 uv = u4[d4];
#pragma unroll
        for (int it = 0; it < ITEMS; it++) {
            float4 nv = shn4[it * (DIM / 4) + d4];
            acc[it] += uv.x * nv.x + uv.y * nv.y + uv.z * nv.z + uv.w * nv.w;
        }
    }

#pragma unroll
    for (int it = 0; it < ITEMS; it++) shout[it][tid] = acc[it];
    __syncthreads();

    for (int idx = tid; idx < BATCH * ITEMS; idx += BATCH) {
        int bb = idx >> 5, it = idx & 31;
        int item = i0 + it;
        if (item < NITEM)
            out[(size_t)bb * NITEM + item] = shout[it][bb] + __ldg(out_bias + item);
    }
}

// ---------------- launch (single stream — graph-capture safe) --------------------
extern "C" void kernel_launch(void* const* d_in, const int* in_sizes, int n_in,
                              void* d_out, int out_size) {
    const int*   edge_idx  = (const int*)d_in[0];
    const int*   edge_type = (const int*)d_in[1];
    const int*   seed_ids  = (const int*)d_in[2];
    const int*   seed_len  = (const int*)d_in[3];
    const float* basis     = (const float*)d_in[5];
    const float* att       = (const float*)d_in[6];
    const float* root      = (const float*)d_in[7];
    const float* rgcn_bias = (const float*)d_in[8];
    const float* attn_a    = (const float*)d_in[9];
    const float* attn_b    = (const float*)d_in[10];
    const float* out_bias  = (const float*)d_in[11];
    float* out = (float*)d_out;

    int prep_n = NITEM * (DIM / 4) > NEN ? NITEM * (DIM / 4) : NEN;
    k_prep   <<<(prep_n + 255) / 256, 256>>>();
    k_mark   <<<(BATCH * SEQL + 255) / 256, 256>>>(seed_ids);
    k_hist   <<<(NE / 4 + 255) / 256, 256>>>(edge_idx);
    k_scan1  <<<NBLK, SB>>>();
    k_scan2  <<<1, 64>>>();
    k_scan3  <<<(NEN + 255) / 256, 256>>>();
    k_scatter<<<(NE / 4 + 255) / 256, 256>>>(edge_idx, edge_type);
    k_gather <<<(NEN * 32 + 255) / 256, 256>>>(basis, att);
    k_fin    <<<(NEN * (DIM / 4) + 255) / 256, 256>>>(root, rgcn_bias);
    k_pool   <<<BATCH, DIM>>>(seed_ids, seed_len, attn_a, attn_b);
    k_score  <<<(NITEM + ITEMS - 1) / ITEMS, BATCH>>>(out_bias, out);
}

// round 14
// speedup vs baseline: 2.5012x; 1.0660x over previous
#include <cuda_runtime.h>
#include <cstdint>

#define NEN   64368
#define NREL  12
#define DIM   128
#define NB    8
#define NITEM 6924
#define NE    1000000
#define BATCH 128
#define SEQL  32

#define SB    1024                       // scan block size
#define NBLK  ((NEN + SB - 1) / SB)      // 63 scan blocks

// ---------------- scratch (no cudaMalloc allowed) ----------------
__device__ __align__(16) float g_aggr[(size_t)NEN * DIM];   // only live rows touched
__device__ __align__(16) float g_u[BATCH * DIM];
__device__ int g_need[NEN];       // 1 if node row is live (item or seed)
__device__ int g_scnt[NEN];       // per-src filtered out-degree
__device__ int g_deg[NEN];        // per-dst filtered in-degree
__device__ int g_off[NEN + 1];    // CSR offsets by src (filtered edges)
__device__ int g_cur[NEN];        // scatter cursors
__device__ int g_sorted[NE];      // packed (type<<16)|dst, grouped by src
__device__ int g_tmp[NEN];        // per-element exclusive prefix within scan block
__device__ int g_bsum[NBLK];      // per-block sums

// ---------------- phase 0: init masks/counters + zero item aggr rows -------------
__global__ void k_prep() {
    int i = blockIdx.x * blockDim.x + threadIdx.x;
    if (i < NEN) {
        g_scnt[i] = 0;
        g_deg[i]  = 0;
        g_need[i] = (i < NITEM) ? 1 : 0;
    }
    if (i < NITEM * (DIM / 4))
        ((float4*)g_aggr)[i] = make_float4(0.f, 0.f, 0.f, 0.f);
}

// ---------------- phase 1: mark seed rows >= NITEM, zero their aggr --------------
__global__ void k_mark(const int* __restrict__ seed_ids) {
    int i = blockIdx.x * blockDim.x + threadIdx.x;
    if (i >= BATCH * SEQL) return;
    int id = __ldg(seed_ids + i);
    if (id >= NITEM && id < NEN) {
        if (atomicExch(&g_need[id], 1) == 0) {
            float4* row = (float4*)(g_aggr + (size_t)id * DIM);
            for (int j = 0; j < DIM / 4; j++) row[j] = make_float4(0.f, 0.f, 0.f, 0.f);
        }
    }
}

// ---------------- phase 2: filtered histograms (4 edges/thread) ------------------
__global__ void k_hist(const int* __restrict__ ei) {
    int t = blockIdx.x * blockDim.x + threadIdx.x;
    if (t >= NE / 4) return;
    int4 s4 = __ldg((const int4*)ei + t);
    int4 d4 = __ldg((const int4*)(ei + NE) + t);
    if (__ldg(g_need + d4.x)) { atomicAdd(&g_scnt[s4.x], 1); atomicAdd(&g_deg[d4.x], 1); }
    if (__ldg(g_need + d4.y)) { atomicAdd(&g_scnt[s4.y], 1); atomicAdd(&g_deg[d4.y], 1); }
    if (__ldg(g_need + d4.z)) { atomicAdd(&g_scnt[s4.z], 1); atomicAdd(&g_deg[d4.z], 1); }
    if (__ldg(g_need + d4.w)) { atomicAdd(&g_scnt[s4.w], 1); atomicAdd(&g_deg[d4.w], 1); }
}

// ---------------- phase 3a: per-block scan (63 blocks x 1024) --------------------
__global__ void k_scan1() {
    __shared__ int s[SB];
    int t = threadIdx.x;
    int g = blockIdx.x * SB + t;
    int v = (g < NEN) ? g_scnt[g] : 0;
    s[t] = v;
    __syncthreads();
#pragma unroll
    for (int o = 1; o < SB; o <<= 1) {
        int x = (t >= o) ? s[t - o] : 0;
        __syncthreads();
        s[t] += x;
        __syncthreads();
    }
    if (g < NEN) g_tmp[g] = s[t] - v;            // exclusive within block
    if (t == SB - 1) g_bsum[blockIdx.x] = s[t];  // block total
}

// ---------------- phase 3b: add block offsets (block-sum scan recomputed inline) -
__global__ void k_scan3() {
    __shared__ int sboff[NBLK];
    int t = threadIdx.x;
    // every block redoes the tiny 63-element exclusive scan (cheap, removes a kernel)
    if (t < NBLK) sboff[t] = g_bsum[t];
    __syncthreads();
    if (t == 0) {
        int run = 0;
#pragma unroll
        for (int i = 0; i < NBLK; i++) { int c = sboff[i]; sboff[i] = run; run += c; }
    }
    __syncthreads();
    int g = blockIdx.x * blockDim.x + t;
    if (g >= NEN) return;
    int off = g_tmp[g] + sboff[g / SB];
    g_off[g] = off;
    g_cur[g] = off;
    if (g == NEN - 1) g_off[NEN] = off + g_scnt[g];
}

// ---------------- phase 4: filtered scatter, grouped by src ----------------------
__global__ void k_scatter(const int* __restrict__ ei, const int* __restrict__ et) {
    int t = blockIdx.x * blockDim.x + threadIdx.x;
    if (t >= NE / 4) return;
    int4 s4 = __ldg((const int4*)ei + t);
    int4 d4 = __ldg((const int4*)(ei + NE) + t);
    int4 t4 = __ldg((const int4*)et + t);
    int p;
    if (__ldg(g_need + d4.x)) { p = atomicAdd(&g_cur[s4.x], 1); g_sorted[p] = (t4.x << 16) | d4.x; }
    if (__ldg(g_need + d4.y)) { p = atomicAdd(&g_cur[s4.y], 1); g_sorted[p] = (t4.y << 16) | d4.y; }
    if (__ldg(g_need + d4.z)) { p = atomicAdd(&g_cur[s4.z], 1); g_sorted[p] = (t4.z << 16) | d4.z; }
    if (__ldg(g_need + d4.w)) { p = atomicAdd(&g_cur[s4.w], 1); g_sorted[p] = (t4.w << 16) | d4.w; }
}

// ---------------- phase 5: fused msg-compute + scatter-add (1 warp per src) ------
__global__ void k_gather(const float* __restrict__ basis, const float* __restrict__ att) {
    __shared__ float s_att[NREL * NB];
    int tid = threadIdx.x;
    if (tid < NREL * NB) s_att[tid] = att[tid];
    __syncthreads();

    int src  = (blockIdx.x * blockDim.x + tid) >> 5;
    int lane = tid & 31;
    if (src >= NEN) return;

    int beg = __ldg(g_off + src);
    int end = __ldg(g_off + src + 1);
    if (beg == end) return;

    const float4* b4 = (const float4*)basis;
    float4 bb[NB];
#pragma unroll
    for (int b = 0; b < NB; b++)
        bb[b] = __ldg(b4 + ((size_t)b * NEN + src) * (DIM / 4) + lane);

    int k = beg;
    for (; k + 1 < end; k += 2) {
        int p0 = __ldg(g_sorted + k);
        int p1 = __ldg(g_sorted + k + 1);
        int t0 = p0 >> 16, d0 = p0 & 0xFFFF;
        int t1 = p1 >> 16, d1 = p1 & 0xFFFF;
        float4 m0 = make_float4(0.f, 0.f, 0.f, 0.f);
        float4 m1 = make_float4(0.f, 0.f, 0.f, 0.f);
#pragma unroll
        for (int b = 0; b < NB; b++) {
            float c0 = s_att[t0 * NB + b];
            float c1 = s_att[t1 * NB + b];
            m0.x += c0 * bb[b].x; m0.y += c0 * bb[b].y;
            m0.z += c0 * bb[b].z; m0.w += c0 * bb[b].w;
            m1.x += c1 * bb[b].x; m1.y += c1 * bb[b].y;
            m1.z += c1 * bb[b].z; m1.w += c1 * bb[b].w;
        }
        float* a0 = g_aggr + (size_t)d0 * DIM + lane * 4;
        float* a1 = g_aggr + (size_t)d1 * DIM + lane * 4;
        asm volatile("red.global.add.v4.f32 [%0], {%1,%2,%3,%4};"
                     :: "l"(a0), "f"(m0.x), "f"(m0.y), "f"(m0.z), "f"(m0.w) : "memory");
        asm volatile("red.global.add.v4.f32 [%0], {%1,%2,%3,%4};"
                     :: "l"(a1), "f"(m1.x), "f"(m1.y), "f"(m1.z), "f"(m1.w) : "memory");
    }
    if (k < end) {
        int p0 = __ldg(g_sorted + k);
        int t0 = p0 >> 16, d0 = p0 & 0xFFFF;
        float4 m0 = make_float4(0.f, 0.f, 0.f, 0.f);
#pragma unroll
        for (int b = 0; b < NB; b++) {
            float c0 = s_att[t0 * NB + b];
            m0.x += c0 * bb[b].x; m0.y += c0 * bb[b].y;
            m0.z += c0 * bb[b].z; m0.w += c0 * bb[b].w;
        }
        float* a0 = g_aggr + (size_t)d0 * DIM + lane * 4;
        asm volatile("red.global.add.v4.f32 [%0], {%1,%2,%3,%4};"
                     :: "l"(a0), "f"(m0.x), "f"(m0.y), "f"(m0.z), "f"(m0.w) : "memory");
    }
}

// ---------------- phase 6: attention pooling, finalize inline --------------------
__global__ void k_pool(const int* __restrict__ seed_ids, const int* __restrict__ seed_len,
                       const float* __restrict__ A, const float* __restrict__ bvec,
                       const float* __restrict__ root, const float* __restrict__ bias) {
    __shared__ float sh_h[SEQL][DIM];
    __shared__ float sh_t[SEQL][DIM + 1];
    __shared__ float sh_e[SEQL];
    __shared__ float sh_attn[SEQL];
    __shared__ int   sid[SEQL];
    __shared__ float sinv[SEQL];

    int b = blockIdx.x;
    int j = threadIdx.x;
    int len = __ldg(seed_len + b);

    if (j < SEQL) {
        int id = __ldg(seed_ids + b * SEQL + j);
        sid[j]  = id;
        sinv[j] = 1.f / fmaxf((float)__ldg(g_deg + id), 1.f);
    }
    __syncthreads();

    float bsj = __ldg(bias + j);
#pragma unroll
    for (int l = 0; l < SEQL; l++) {
        size_t o = (size_t)sid[l] * DIM + j;
        sh_h[l][j] = g_aggr[o] * sinv[l] + __ldg(root + o) + bsj;   // finalize inline
    }
    __syncthreads();

    float pe[SEQL];
#pragma unroll
    for (int l = 0; l < SEQL; l++) pe[l] = 0.f;
    for (int d = 0; d < DIM; d++) {
        float a = __ldg(A + d * DIM + j);
#pragma unroll
        for (int l = 0; l < SEQL; l++) pe[l] += sh_h[l][d] * a;
    }
    float bv = __ldg(bvec + j);
#pragma unroll
    for (int l = 0; l < SEQL; l++) sh_t[l][j] = tanhf(pe[l]) * bv;
    __syncthreads();

    if (j < SEQL) {
        float s = 0.f;
        for (int d = 0; d < DIM; d++) s += sh_t[j][d];
        sh_e[j] = s;
    }
    __syncthreads();

    if (j < 32) {
        float val = (j < len) ? sh_e[j] : -1e30f;
        float m = val;
#pragma unroll
        for (int o = 16; o; o >>= 1) m = fmaxf(m, __shfl_xor_sync(0xffffffffu, m, o));
        float ex = (j < len) ? expf(val - m) : 0.f;
        float s = ex;
#pragma unroll
        for (int o = 16; o; o >>= 1) s += __shfl_xor_sync(0xffffffffu, s, o);
        sh_attn[j] = (len > 0) ? ex / s : 0.f;
    }
    __syncthreads();

    float u = 0.f;
#pragma unroll
    for (int l = 0; l < SEQL; l++) u += sh_attn[l] * sh_h[l][j];
    g_u[b * DIM + j] = u;
}

// ---------------- phase 7: scores = u @ items.T + out_bias, finalize inline ------
#define ITEMS 32
__global__ void k_score(const float* __restrict__ out_bias, float* __restrict__ out,
                        const float* __restrict__ root, const float* __restrict__ bias) {
    __shared__ float shn[ITEMS * DIM];
    __shared__ float shout[ITEMS][BATCH + 1];
    __shared__ float sinv[ITEMS];

    int tid = threadIdx.x;
    int i0  = blockIdx.x * ITEMS;

    if (tid < ITEMS) {
        int item = i0 + tid;
        sinv[tid] = (item < NITEM)
                  ? 1.f / fmaxf((float)__ldg(g_deg + item), 1.f) : 0.f;
    }
    __syncthreads();

    for (int idx = tid; idx < ITEMS * DIM; idx += BATCH) {
        int it = idx >> 7, d = idx & 127;
        int item = i0 + it;
        float v = 0.f;
        if (item < NITEM) {
            size_t o = (size_t)item * DIM + d;
            v = g_aggr[o] * sinv[it] + __ldg(root + o) + __ldg(bias + d);  // finalize inline
        }
        shn[idx] = v;
    }
    __syncthreads();

    float acc[ITEMS];
#pragma unroll
    for (int it = 0; it < ITEMS; it++) acc[it] = 0.f;

    const float4* u4   = (const float4*)(g_u + tid * DIM);
    const float4* shn4 = (const float4*)shn;
#pragma unroll 4
    for (int d4 = 0; d4 < DIM / 4; d4++) {
        float4 uv = u4[d4];
#pragma unroll
        for (int it = 0; it < ITEMS; it++) {
            float4 nv = shn4[it * (DIM / 4) + d4];
            acc[it] += uv.x * nv.x + uv.y * nv.y + uv.z * nv.z + uv.w * nv.w;
        }
    }

#pragma unroll
    for (int it = 0; it < ITEMS; it++) shout[it][tid] = acc[it];
    __syncthreads();

    for (int idx = tid; idx < BATCH * ITEMS; idx += BATCH) {
        int bb = idx >> 5, it = idx & 31;
        int item = i0 + it;
        if (item < NITEM)
            out[(size_t)bb * NITEM + item] = shout[it][bb] + __ldg(out_bias + item);
    }
}

// ---------------- launch (single stream — graph-capture safe) --------------------
extern "C" void kernel_launch(void* const* d_in, const int* in_sizes, int n_in,
                              void* d_out, int out_size) {
    const int*   edge_idx  = (const int*)d_in[0];
    const int*   edge_type = (const int*)d_in[1];
    const int*   seed_ids  = (const int*)d_in[2];
    const int*   seed_len  = (const int*)d_in[3];
    const float* basis     = (const float*)d_in[5];
    const float* att       = (const float*)d_in[6];
    const float* root      = (const float*)d_in[7];
    const float* rgcn_bias = (const float*)d_in[8];
    const float* attn_a    = (const float*)d_in[9];
    const float* attn_b    = (const float*)d_in[10];
    const float* out_bias  = (const float*)d_in[11];
    float* out = (float*)d_out;

    int prep_n = NITEM * (DIM / 4) > NEN ? NITEM * (DIM / 4) : NEN;
    k_prep   <<<(prep_n + 255) / 256, 256>>>();
    k_mark   <<<(BATCH * SEQL + 255) / 256, 256>>>(seed_ids);
    k_hist   <<<(NE / 4 + 255) / 256, 256>>>(edge_idx);
    k_scan1  <<<NBLK, SB>>>();
    k_scan3  <<<(NEN + 255) / 256, 256>>>();
    k_scatter<<<(NE / 4 + 255) / 256, 256>>>(edge_idx, edge_type);
    k_gather <<<(NEN * 32 + 255) / 256, 256>>>(basis, att);
    k_pool   <<<BATCH, DIM>>>(seed_ids, seed_len, attn_a, attn_b, root, rgcn_bias);
    k_score  <<<(NITEM + ITEMS - 1) / ITEMS, BATCH>>>(out_bias, out, root, rgcn_bias);
}